// round 2
// baseline (speedup 1.0000x reference)
#include <cuda_runtime.h>
#include <cstdint>

// Problem constants
#define BATCH 20
#define CHN   60
#define HH    264
#define WW    264
#define PLANE (HH*WW)            // 69696

// Conv tiling
#define TW    132                // tile width  (264/2)
#define TH    4                  // tile height (264/66)
#define OCT   5                  // out-channels per thread
#define OCG   12                 // oc groups (12*5 = 60)
#define PX    12                 // pixels per thread (one row segment)
#define PXG   44                 // pixel groups: (132/12)=11 per row * 4 rows
#define THREADS (OCG*PXG)        // 528
#define SXSTRIDE 136             // padded smem row stride (mult of 4 for float4)

// Scratch (device globals: no allocation allowed)
__device__ float g_gap[BATCH*CHN*9];        // [b][c][k]
__device__ float g_fbuf[3*20*20*9];         // [g][j][i][k]
__device__ float g_F2[60*60*9*2];           // [cin][oc][k][dup2]  (duplicated pairs)

// ---------------- packed f32x2 helpers ----------------
__device__ __forceinline__ unsigned long long pack2(float lo, float hi) {
    unsigned long long r;
    asm("mov.b64 %0, {%1, %2};" : "=l"(r) : "f"(lo), "f"(hi));
    return r;
}
__device__ __forceinline__ void unpack2(unsigned long long v, float& lo, float& hi) {
    asm("mov.b64 {%0, %1}, %2;" : "=f"(lo), "=f"(hi) : "l"(v));
}
__device__ __forceinline__ unsigned long long ffma2(unsigned long long a,
                                                    unsigned long long b,
                                                    unsigned long long c) {
    unsigned long long d;
    asm("fma.rn.f32x2 %0, %1, %2, %3;" : "=l"(d) : "l"(a), "l"(b), "l"(c));
    return d;
}

// ---------------- Kernel 1: 3x3 adaptive avg pool (block means over 88x88) ----------------
__global__ void gap_kernel(const float* __restrict__ x) {
    const int bc = blockIdx.x;                       // 0..1199  = b*60+c
    const float* p = x + (size_t)bc * PLANE;
    float s[9];
#pragma unroll
    for (int r = 0; r < 9; ++r) s[r] = 0.f;
    for (int i = threadIdx.x; i < PLANE; i += blockDim.x) {
        int h = i / WW, w = i - h * WW;
        int r = (h / 88) * 3 + (w / 88);
        s[r] += p[i];
    }
    __shared__ float red[9 * 8];
    const unsigned lane = threadIdx.x & 31u, warp = threadIdx.x >> 5;
#pragma unroll
    for (int r = 0; r < 9; ++r) {
        float v = s[r];
#pragma unroll
        for (int off = 16; off > 0; off >>= 1) v += __shfl_down_sync(0xffffffffu, v, off);
        if (lane == 0) red[r * 8 + warp] = v;
    }
    __syncthreads();
    if (threadIdx.x < 9) {
        float v = 0.f;
#pragma unroll
        for (int w = 0; w < 8; ++w) v += red[threadIdx.x * 8 + w];
        g_gap[bc * 9 + threadIdx.x] = v * (1.0f / 7744.0f);
    }
}

// ---------------- Kernel 2a: dynamic filters f[g][j][i][k] = tanh(para*(gap.w + b)) ----------------
__global__ void filt1_kernel(const float* __restrict__ w1, const float* __restrict__ b1,
                             const float* __restrict__ w2, const float* __restrict__ b2,
                             const float* __restrict__ w3, const float* __restrict__ b3,
                             const float* __restrict__ p1, const float* __restrict__ p2,
                             const float* __restrict__ p3) {
    int idx = blockIdx.x * blockDim.x + threadIdx.x;
    if (idx >= 3 * 20 * 20 * 9) return;
    int k = idx % 9;
    int i = (idx / 9) % 20;
    int j = (idx / 180) % 20;
    int g = idx / 3600;
    const float* w = (g == 0) ? w1 : (g == 1) ? w2 : w3;
    const float* bb = (g == 0) ? b1 : (g == 1) ? b2 : b3;
    const float para = (g == 0) ? p1[0] : (g == 1) ? p2[0] : p3[0];
    float acc = bb[i];
    const float* gp = g_gap + (j * 60) * 9 + k;      // gap[j][c][k], stride 9 over c
    const float* wr = w + i * 60;
#pragma unroll 10
    for (int c = 0; c < 60; ++c) acc += gp[c * 9] * wr[c];
    g_fbuf[idx] = tanhf(para * acc);
}

// ---------------- Kernel 2b: effective filters F[cin][oc][k] (duplicated pairs) ----------------
__global__ void filt2_kernel(const float* __restrict__ w_out) {
    int idx = blockIdx.x * blockDim.x + threadIdx.x;
    if (idx >= 60 * 60 * 9) return;
    int k = idx % 9;
    int cin = (idx / 9) % 60;
    int oc = idx / 540;
    int g = cin / 20, i = cin % 20;
    float s = 0.f;
#pragma unroll
    for (int j = 0; j < 20; ++j)
        s += w_out[oc * 60 + g * 20 + j] * g_fbuf[((g * 20 + j) * 20 + i) * 9 + k];
    float* dst = g_F2 + cin * 1080 + (oc * 9 + k) * 2;
    dst[0] = s;
    dst[1] = s;
}

// ---------------- Kernel 3: fused 60->60 3x3 conv, packed f32x2 ----------------
__global__ void __launch_bounds__(THREADS, 1)
conv_kernel(const float* __restrict__ x, const float* __restrict__ b_out,
            float* __restrict__ out) {
    const int tx0 = blockIdx.x * TW;
    const int ty0 = blockIdx.y * TH;
    const int b   = blockIdx.z;
    const int tid = threadIdx.x;
    const int ocg = tid / PXG;                 // 0..11
    const int pxg = tid % PXG;                 // 0..43
    const int prow = pxg / 11;                 // 0..3
    const int pcol = (pxg % 11) * PX;          // 0..120

    __shared__ __align__(16) float s_x[(TH + 2) * SXSTRIDE];   // 6 x 136
    __shared__ __align__(16) float s_F[1080];                   // per-cin dup'd filters

    unsigned long long acc[OCT][PX / 2];
#pragma unroll
    for (int o = 0; o < OCT; ++o)
#pragma unroll
        for (int j = 0; j < PX / 2; ++j) acc[o][j] = 0ull;

    for (int cin = 0; cin < CHN; ++cin) {
        __syncthreads();
        // cooperative load of (TH+2) x (TW+2) input tile, zero-padded
        {
            const float* xp = x + ((size_t)(b * CHN + cin)) * PLANE;
            for (int i = tid; i < (TH + 2) * (TW + 2); i += THREADS) {
                int r = i / (TW + 2), c = i - r * (TW + 2);
                int gy = ty0 - 1 + r, gx = tx0 - 1 + c;
                float v = 0.f;
                if ((unsigned)gy < (unsigned)HH && (unsigned)gx < (unsigned)WW)
                    v = xp[gy * WW + gx];
                s_x[r * SXSTRIDE + c] = v;
            }
            const float* Fp = g_F2 + cin * 1080;
            for (int i = tid; i < 1080; i += THREADS) s_F[i] = Fp[i];
        }
        __syncthreads();

#pragma unroll
        for (int rr = 0; rr < 3; ++rr) {
            const float* srow = &s_x[(prow + rr) * SXSTRIDE + pcol];
            float4 a0 = *reinterpret_cast<const float4*>(srow);
            float4 a1 = *reinterpret_cast<const float4*>(srow + 4);
            float4 a2 = *reinterpret_cast<const float4*>(srow + 8);
            float2 a3 = *reinterpret_cast<const float2*>(srow + 12);
            float xv[14];
            xv[0] = a0.x; xv[1] = a0.y; xv[2] = a0.z; xv[3] = a0.w;
            xv[4] = a1.x; xv[5] = a1.y; xv[6] = a1.z; xv[7] = a1.w;
            xv[8] = a2.x; xv[9] = a2.y; xv[10] = a2.z; xv[11] = a2.w;
            xv[12] = a3.x; xv[13] = a3.y;
            unsigned long long xp2[13];
#pragma unroll
            for (int i = 0; i < 13; ++i) xp2[i] = pack2(xv[i], xv[i + 1]);

#pragma unroll
            for (int o = 0; o < OCT; ++o) {
                const unsigned long long* frow = reinterpret_cast<const unsigned long long*>(
                    &s_F[((ocg * OCT + o) * 9 + rr * 3) * 2]);
#pragma unroll
                for (int kw = 0; kw < 3; ++kw) {
                    unsigned long long ff = frow[kw];          // ld.shared.b64 (broadcast)
#pragma unroll
                    for (int j = 0; j < PX / 2; ++j)
                        acc[o][j] = ffma2(xp2[2 * j + kw], ff, acc[o][j]);
                }
            }
        }
    }

    // epilogue: add bias, store 12 contiguous fp32 per oc (3x float4)
    const int h = ty0 + prow;
    const int w0 = tx0 + pcol;
#pragma unroll
    for (int o = 0; o < OCT; ++o) {
        const int oc = ocg * OCT + o;
        const float bo = b_out[oc];
        float v[12];
#pragma unroll
        for (int j = 0; j < PX / 2; ++j) {
            float lo, hi;
            unpack2(acc[o][j], lo, hi);
            v[2 * j] = lo + bo;
            v[2 * j + 1] = hi + bo;
        }
        float* op = out + (((size_t)(b * CHN + oc)) * HH + h) * WW + w0;
        reinterpret_cast<float4*>(op)[0] = make_float4(v[0], v[1], v[2], v[3]);
        reinterpret_cast<float4*>(op)[1] = make_float4(v[4], v[5], v[6], v[7]);
        reinterpret_cast<float4*>(op)[2] = make_float4(v[8], v[9], v[10], v[11]);
    }
}

// ---------------- launch ----------------
extern "C" void kernel_launch(void* const* d_in, const int* in_sizes, int n_in,
                              void* d_out, int out_size) {
    const float* x     = (const float*)d_in[0];
    const float* w1    = (const float*)d_in[1];
    const float* b1    = (const float*)d_in[2];
    const float* w2    = (const float*)d_in[3];
    const float* b2    = (const float*)d_in[4];
    const float* w3    = (const float*)d_in[5];
    const float* b3    = (const float*)d_in[6];
    const float* p1    = (const float*)d_in[7];
    const float* p2    = (const float*)d_in[8];
    const float* p3    = (const float*)d_in[9];
    const float* w_out = (const float*)d_in[10];
    const float* b_out = (const float*)d_in[11];
    float* out = (float*)d_out;

    gap_kernel<<<BATCH * CHN, 256>>>(x);
    filt1_kernel<<<(10800 + 255) / 256, 256>>>(w1, b1, w2, b2, w3, b3, p1, p2, p3);
    filt2_kernel<<<(32400 + 255) / 256, 256>>>(w_out);
    dim3 grid(WW / TW, HH / TH, BATCH);   // (2, 66, 20)
    conv_kernel<<<grid, THREADS>>>(x, b_out, out);
}

// round 4
// speedup vs baseline: 1.3378x; 1.3378x over previous
#include <cuda_runtime.h>
#include <cstdint>

// Problem constants
#define BATCH 20
#define CHN   60
#define HH    264
#define WW    264
#define PLANE (HH*WW)            // 69696

// Conv tiling
#define TW    132
#define TH    4
#define OCT   5
#define OCG   12
#define PX    12
#define PXG   44
#define THREADS (OCG*PXG)        // 528
#define SXSTRIDE 136
#define TILE_ELEMS ((TH+2)*(TW+2))   // 804
#define FELEMS 1080

// Scratch (device globals: no allocation allowed)
__device__ float g_gap[BATCH*CHN*9];
__device__ float g_fbuf[3*20*20*9];
__device__ float g_F2[60*60*9*2];    // [cin][oc][k][dup2]

// ---------------- packed f32x2 helpers ----------------
__device__ __forceinline__ unsigned long long pack2(float lo, float hi) {
    unsigned long long r;
    asm("mov.b64 %0, {%1, %2};" : "=l"(r) : "f"(lo), "f"(hi));
    return r;
}
__device__ __forceinline__ void unpack2(unsigned long long v, float& lo, float& hi) {
    asm("mov.b64 {%0, %1}, %2;" : "=f"(lo), "=f"(hi) : "l"(v));
}
__device__ __forceinline__ unsigned long long ffma2(unsigned long long a,
                                                    unsigned long long b,
                                                    unsigned long long c) {
    unsigned long long d;
    asm("fma.rn.f32x2 %0, %1, %2, %3;" : "=l"(d) : "l"(a), "l"(b), "l"(c));
    return d;
}

// ---------------- Kernel 1: 3x3 adaptive avg pool ----------------
__global__ void gap_kernel(const float* __restrict__ x) {
    const int bc = blockIdx.x;
    const float* p = x + (size_t)bc * PLANE;
    float s[9];
#pragma unroll
    for (int r = 0; r < 9; ++r) s[r] = 0.f;
    for (int i = threadIdx.x; i < PLANE; i += blockDim.x) {
        int h = i / WW, w = i - h * WW;
        int r = (h / 88) * 3 + (w / 88);
        s[r] += p[i];
    }
    __shared__ float red[9 * 8];
    const unsigned lane = threadIdx.x & 31u, warp = threadIdx.x >> 5;
#pragma unroll
    for (int r = 0; r < 9; ++r) {
        float v = s[r];
#pragma unroll
        for (int off = 16; off > 0; off >>= 1) v += __shfl_down_sync(0xffffffffu, v, off);
        if (lane == 0) red[r * 8 + warp] = v;
    }
    __syncthreads();
    if (threadIdx.x < 9) {
        float v = 0.f;
#pragma unroll
        for (int w = 0; w < 8; ++w) v += red[threadIdx.x * 8 + w];
        g_gap[bc * 9 + threadIdx.x] = v * (1.0f / 7744.0f);
    }
}

// ---------------- Kernel 2a: dynamic filters ----------------
__global__ void filt1_kernel(const float* __restrict__ w1, const float* __restrict__ b1,
                             const float* __restrict__ w2, const float* __restrict__ b2,
                             const float* __restrict__ w3, const float* __restrict__ b3,
                             const float* __restrict__ p1, const float* __restrict__ p2,
                             const float* __restrict__ p3) {
    int idx = blockIdx.x * blockDim.x + threadIdx.x;
    if (idx >= 3 * 20 * 20 * 9) return;
    int k = idx % 9;
    int i = (idx / 9) % 20;
    int j = (idx / 180) % 20;
    int g = idx / 3600;
    const float* w = (g == 0) ? w1 : (g == 1) ? w2 : w3;
    const float* bb = (g == 0) ? b1 : (g == 1) ? b2 : b3;
    const float para = (g == 0) ? p1[0] : (g == 1) ? p2[0] : p3[0];
    float acc = bb[i];
    const float* gp = g_gap + (j * 60) * 9 + k;
    const float* wr = w + i * 60;
#pragma unroll 10
    for (int c = 0; c < 60; ++c) acc += gp[c * 9] * wr[c];
    g_fbuf[idx] = tanhf(para * acc);
}

// ---------------- Kernel 2b: effective filters ----------------
__global__ void filt2_kernel(const float* __restrict__ w_out) {
    int idx = blockIdx.x * blockDim.x + threadIdx.x;
    if (idx >= 60 * 60 * 9) return;
    int k = idx % 9;
    int cin = (idx / 9) % 60;
    int oc = idx / 540;
    int g = cin / 20, i = cin % 20;
    float s = 0.f;
#pragma unroll
    for (int j = 0; j < 20; ++j)
        s += w_out[oc * 60 + g * 20 + j] * g_fbuf[((g * 20 + j) * 20 + i) * 9 + k];
    float* dst = g_F2 + cin * 1080 + (oc * 9 + k) * 2;
    dst[0] = s;
    dst[1] = s;
}

// ---------------- Kernel 3: fused conv, software-pipelined ----------------
__global__ void __launch_bounds__(THREADS, 1)
conv_kernel(const float* __restrict__ x, const float* __restrict__ b_out,
            float* __restrict__ out) {
    const int tx0 = blockIdx.x * TW;
    const int ty0 = blockIdx.y * TH;
    const int b   = blockIdx.z;
    const int tid = threadIdx.x;
    const int ocg = tid / PXG;
    const int pxg = tid % PXG;
    const int prow = pxg / 11;
    const int pcol = (pxg % 11) * PX;

    __shared__ __align__(16) float s_x[2][(TH + 2) * SXSTRIDE];
    __shared__ __align__(16) float s_F[2][FELEMS];

    // ---- precompute tile-load slots (iteration-invariant) ----
    int off0, d0; bool p0;
    int off1, d1; bool p1v, w1ok;
    {
        int i = tid;
        int r = i / (TW + 2), c = i - r * (TW + 2);
        int gy = ty0 - 1 + r, gx = tx0 - 1 + c;
        p0 = ((unsigned)gy < (unsigned)HH) && ((unsigned)gx < (unsigned)WW);
        off0 = p0 ? (gy * WW + gx) : 0;
        d0 = r * SXSTRIDE + c;
    }
    {
        int i = tid + THREADS;
        w1ok = i < TILE_ELEMS;                     // this thread owns a second slot
        int r = i / (TW + 2), c = i - r * (TW + 2);
        int gy = ty0 - 1 + r, gx = tx0 - 1 + c;
        p1v = w1ok && ((unsigned)gy < (unsigned)HH) && ((unsigned)gx < (unsigned)WW);
        off1 = p1v ? (gy * WW + gx) : 0;
        d1 = w1ok ? (r * SXSTRIDE + c) : 0;        // never written when !w1ok
    }
    const int f0 = tid, f1 = tid + THREADS, f2 = tid + 2 * THREADS;
    const bool f2ok = f2 < FELEMS;

    unsigned long long acc[OCT][PX / 2];
#pragma unroll
    for (int o = 0; o < OCT; ++o)
#pragma unroll
        for (int j = 0; j < PX / 2; ++j) acc[o][j] = 0ull;

    const float* xp = x + ((size_t)(b * CHN)) * PLANE;   // cin 0 plane
    const float* Fp = g_F2;

    // ---- prologue: load cin=0 into buffer 0 ----
    {
        float v0 = p0 ? __ldg(xp + off0) : 0.f;
        float v1 = p1v ? __ldg(xp + off1) : 0.f;
        float fa = __ldg(Fp + f0);
        float fb = __ldg(Fp + f1);
        float fc = f2ok ? __ldg(Fp + f2) : 0.f;
        s_x[0][d0] = v0;
        if (w1ok) s_x[0][d1] = v1;                 // pad positions correctly get 0
        s_F[0][f0] = fa;
        s_F[0][f1] = fb;
        if (f2ok) s_F[0][f2] = fc;
    }
    __syncthreads();

#pragma unroll 2
    for (int cin = 0; cin < CHN; ++cin) {
        const int cur = cin & 1;
        const int nxt = cur ^ 1;

        // ---- prefetch cin+1 into registers (latency hidden by compute) ----
        float nx0 = 0.f, nx1 = 0.f, nfa = 0.f, nfb = 0.f, nfc = 0.f;
        const bool more = (cin + 1) < CHN;
        if (more) {
            const float* xq = xp + PLANE;
            const float* Fq = Fp + FELEMS;
            nx0 = p0 ? __ldg(xq + off0) : 0.f;
            nx1 = p1v ? __ldg(xq + off1) : 0.f;
            nfa = __ldg(Fq + f0);
            nfb = __ldg(Fq + f1);
            nfc = f2ok ? __ldg(Fq + f2) : 0.f;
        }

        // ---- compute on current buffers ----
#pragma unroll
        for (int rr = 0; rr < 3; ++rr) {
            const float* srow = &s_x[cur][(prow + rr) * SXSTRIDE + pcol];
            float4 a0 = *reinterpret_cast<const float4*>(srow);
            float4 a1 = *reinterpret_cast<const float4*>(srow + 4);
            float4 a2 = *reinterpret_cast<const float4*>(srow + 8);
            float2 a3 = *reinterpret_cast<const float2*>(srow + 12);
            float xv[14];
            xv[0] = a0.x; xv[1] = a0.y; xv[2] = a0.z; xv[3] = a0.w;
            xv[4] = a1.x; xv[5] = a1.y; xv[6] = a1.z; xv[7] = a1.w;
            xv[8] = a2.x; xv[9] = a2.y; xv[10] = a2.z; xv[11] = a2.w;
            xv[12] = a3.x; xv[13] = a3.y;
            unsigned long long xp2[13];
#pragma unroll
            for (int i = 0; i < 13; ++i) xp2[i] = pack2(xv[i], xv[i + 1]);

#pragma unroll
            for (int o = 0; o < OCT; ++o) {
                const unsigned long long* frow = reinterpret_cast<const unsigned long long*>(
                    &s_F[cur][((ocg * OCT + o) * 9 + rr * 3) * 2]);
#pragma unroll
                for (int kw = 0; kw < 3; ++kw) {
                    unsigned long long ff = frow[kw];
#pragma unroll
                    for (int j = 0; j < PX / 2; ++j)
                        acc[o][j] = ffma2(xp2[2 * j + kw], ff, acc[o][j]);
                }
            }
        }

        // ---- stage prefetched data into the other buffer ----
        if (more) {
            s_x[nxt][d0] = nx0;
            if (w1ok) s_x[nxt][d1] = nx1;
            s_F[nxt][f0] = nfa;
            s_F[nxt][f1] = nfb;
            if (f2ok) s_F[nxt][f2] = nfc;
            xp += PLANE;
            Fp += FELEMS;
        }
        __syncthreads();
    }

    // ---- epilogue ----
    const int h = ty0 + prow;
    const int w0 = tx0 + pcol;
#pragma unroll
    for (int o = 0; o < OCT; ++o) {
        const int oc = ocg * OCT + o;
        const float bo = b_out[oc];
        float v[12];
#pragma unroll
        for (int j = 0; j < PX / 2; ++j) {
            float lo, hi;
            unpack2(acc[o][j], lo, hi);
            v[2 * j] = lo + bo;
            v[2 * j + 1] = hi + bo;
        }
        float* op = out + (((size_t)(b * CHN + oc)) * HH + h) * WW + w0;
        reinterpret_cast<float4*>(op)[0] = make_float4(v[0], v[1], v[2], v[3]);
        reinterpret_cast<float4*>(op)[1] = make_float4(v[4], v[5], v[6], v[7]);
        reinterpret_cast<float4*>(op)[2] = make_float4(v[8], v[9], v[10], v[11]);
    }
}

// ---------------- launch ----------------
extern "C" void kernel_launch(void* const* d_in, const int* in_sizes, int n_in,
                              void* d_out, int out_size) {
    const float* x     = (const float*)d_in[0];
    const float* w1    = (const float*)d_in[1];
    const float* b1    = (const float*)d_in[2];
    const float* w2    = (const float*)d_in[3];
    const float* b2    = (const float*)d_in[4];
    const float* w3    = (const float*)d_in[5];
    const float* b3    = (const float*)d_in[6];
    const float* p1    = (const float*)d_in[7];
    const float* p2    = (const float*)d_in[8];
    const float* p3    = (const float*)d_in[9];
    const float* w_out = (const float*)d_in[10];
    const float* b_out = (const float*)d_in[11];
    float* out = (float*)d_out;

    gap_kernel<<<BATCH * CHN, 256>>>(x);
    filt1_kernel<<<(10800 + 255) / 256, 256>>>(w1, b1, w2, b2, w3, b3, p1, p2, p3);
    filt2_kernel<<<(32400 + 255) / 256, 256>>>(w_out);
    dim3 grid(WW / TW, HH / TH, BATCH);   // (2, 66, 20)
    conv_kernel<<<grid, THREADS>>>(x, b_out, out);
}

// round 5
// speedup vs baseline: 1.3391x; 1.0009x over previous
#include <cuda_runtime.h>
#include <cstdint>

// Problem constants
#define BATCH 20
#define CHN   60
#define HH    264
#define WW    264
#define PLANE (HH*WW)            // 69696

// Conv tiling
#define TW    132
#define TH    4
#define OCT   5
#define OCG   12
#define PX    12
#define PXG   44
#define THREADS (OCG*PXG)        // 528
#define SXSTRIDE 136
#define TILE_ELEMS ((TH+2)*(TW+2))   // 804
#define FELEMS 1080

// Scratch (device globals: no allocation allowed)
__device__ float g_gap[BATCH*CHN*9];
__device__ float g_fbuf[3*20*20*9];
__device__ float g_F2[60*60*9*2];    // [cin][oc][k][dup2]

// ---------------- packed f32x2 helpers ----------------
__device__ __forceinline__ unsigned long long pack2(float lo, float hi) {
    unsigned long long r;
    asm("mov.b64 %0, {%1, %2};" : "=l"(r) : "f"(lo), "f"(hi));
    return r;
}
__device__ __forceinline__ void unpack2(unsigned long long v, float& lo, float& hi) {
    asm("mov.b64 {%0, %1}, %2;" : "=f"(lo), "=f"(hi) : "l"(v));
}
__device__ __forceinline__ unsigned long long ffma2(unsigned long long a,
                                                    unsigned long long b,
                                                    unsigned long long c) {
    unsigned long long d;
    asm("fma.rn.f32x2 %0, %1, %2, %3;" : "=l"(d) : "l"(a), "l"(b), "l"(c));
    return d;
}

// ---------------- Kernel 1: 3x3 adaptive avg pool ----------------
__global__ void gap_kernel(const float* __restrict__ x) {
    const int bc = blockIdx.x;
    const float* p = x + (size_t)bc * PLANE;
    float s[9];
#pragma unroll
    for (int r = 0; r < 9; ++r) s[r] = 0.f;
    for (int i = threadIdx.x; i < PLANE; i += blockDim.x) {
        int h = i / WW, w = i - h * WW;
        int r = (h / 88) * 3 + (w / 88);
        s[r] += p[i];
    }
    __shared__ float red[9 * 8];
    const unsigned lane = threadIdx.x & 31u, warp = threadIdx.x >> 5;
#pragma unroll
    for (int r = 0; r < 9; ++r) {
        float v = s[r];
#pragma unroll
        for (int off = 16; off > 0; off >>= 1) v += __shfl_down_sync(0xffffffffu, v, off);
        if (lane == 0) red[r * 8 + warp] = v;
    }
    __syncthreads();
    if (threadIdx.x < 9) {
        float v = 0.f;
#pragma unroll
        for (int w = 0; w < 8; ++w) v += red[threadIdx.x * 8 + w];
        g_gap[bc * 9 + threadIdx.x] = v * (1.0f / 7744.0f);
    }
}

// ---------------- Kernel 2a: dynamic filters ----------------
__global__ void filt1_kernel(const float* __restrict__ w1, const float* __restrict__ b1,
                             const float* __restrict__ w2, const float* __restrict__ b2,
                             const float* __restrict__ w3, const float* __restrict__ b3,
                             const float* __restrict__ p1, const float* __restrict__ p2,
                             const float* __restrict__ p3) {
    int idx = blockIdx.x * blockDim.x + threadIdx.x;
    if (idx >= 3 * 20 * 20 * 9) return;
    int k = idx % 9;
    int i = (idx / 9) % 20;
    int j = (idx / 180) % 20;
    int g = idx / 3600;
    const float* w = (g == 0) ? w1 : (g == 1) ? w2 : w3;
    const float* bb = (g == 0) ? b1 : (g == 1) ? b2 : b3;
    const float para = (g == 0) ? p1[0] : (g == 1) ? p2[0] : p3[0];
    float acc = bb[i];
    const float* gp = g_gap + (j * 60) * 9 + k;
    const float* wr = w + i * 60;
#pragma unroll 10
    for (int c = 0; c < 60; ++c) acc += gp[c * 9] * wr[c];
    g_fbuf[idx] = tanhf(para * acc);
}

// ---------------- Kernel 2b: effective filters ----------------
__global__ void filt2_kernel(const float* __restrict__ w_out) {
    int idx = blockIdx.x * blockDim.x + threadIdx.x;
    if (idx >= 60 * 60 * 9) return;
    int k = idx % 9;
    int cin = (idx / 9) % 60;
    int oc = idx / 540;
    int g = cin / 20, i = cin % 20;
    float s = 0.f;
#pragma unroll
    for (int j = 0; j < 20; ++j)
        s += w_out[oc * 60 + g * 20 + j] * g_fbuf[((g * 20 + j) * 20 + i) * 9 + k];
    float* dst = g_F2 + cin * 1080 + (oc * 9 + k) * 2;
    dst[0] = s;
    dst[1] = s;
}

// ---------------- Kernel 3: fused conv, software-pipelined ----------------
__global__ void __launch_bounds__(THREADS, 1)
conv_kernel(const float* __restrict__ x, const float* __restrict__ b_out,
            float* __restrict__ out) {
    const int tx0 = blockIdx.x * TW;
    const int ty0 = blockIdx.y * TH;
    const int b   = blockIdx.z;
    const int tid = threadIdx.x;
    const int ocg = tid / PXG;
    const int pxg = tid % PXG;
    const int prow = pxg / 11;
    const int pcol = (pxg % 11) * PX;

    __shared__ __align__(16) float s_x[2][(TH + 2) * SXSTRIDE];
    __shared__ __align__(16) float s_F[2][FELEMS];

    // ---- precompute tile-load slots (iteration-invariant) ----
    int off0, d0; bool p0;
    int off1, d1; bool p1v, w1ok;
    {
        int i = tid;
        int r = i / (TW + 2), c = i - r * (TW + 2);
        int gy = ty0 - 1 + r, gx = tx0 - 1 + c;
        p0 = ((unsigned)gy < (unsigned)HH) && ((unsigned)gx < (unsigned)WW);
        off0 = p0 ? (gy * WW + gx) : 0;
        d0 = r * SXSTRIDE + c;
    }
    {
        int i = tid + THREADS;
        w1ok = i < TILE_ELEMS;                     // this thread owns a second slot
        int r = i / (TW + 2), c = i - r * (TW + 2);
        int gy = ty0 - 1 + r, gx = tx0 - 1 + c;
        p1v = w1ok && ((unsigned)gy < (unsigned)HH) && ((unsigned)gx < (unsigned)WW);
        off1 = p1v ? (gy * WW + gx) : 0;
        d1 = w1ok ? (r * SXSTRIDE + c) : 0;        // never written when !w1ok
    }
    const int f0 = tid, f1 = tid + THREADS, f2 = tid + 2 * THREADS;
    const bool f2ok = f2 < FELEMS;

    unsigned long long acc[OCT][PX / 2];
#pragma unroll
    for (int o = 0; o < OCT; ++o)
#pragma unroll
        for (int j = 0; j < PX / 2; ++j) acc[o][j] = 0ull;

    const float* xp = x + ((size_t)(b * CHN)) * PLANE;   // cin 0 plane
    const float* Fp = g_F2;

    // ---- prologue: load cin=0 into buffer 0 ----
    {
        float v0 = p0 ? __ldg(xp + off0) : 0.f;
        float v1 = p1v ? __ldg(xp + off1) : 0.f;
        float fa = __ldg(Fp + f0);
        float fb = __ldg(Fp + f1);
        float fc = f2ok ? __ldg(Fp + f2) : 0.f;
        s_x[0][d0] = v0;
        if (w1ok) s_x[0][d1] = v1;                 // pad positions correctly get 0
        s_F[0][f0] = fa;
        s_F[0][f1] = fb;
        if (f2ok) s_F[0][f2] = fc;
    }
    __syncthreads();

#pragma unroll 2
    for (int cin = 0; cin < CHN; ++cin) {
        const int cur = cin & 1;
        const int nxt = cur ^ 1;

        // ---- prefetch cin+1 into registers (latency hidden by compute) ----
        float nx0 = 0.f, nx1 = 0.f, nfa = 0.f, nfb = 0.f, nfc = 0.f;
        const bool more = (cin + 1) < CHN;
        if (more) {
            const float* xq = xp + PLANE;
            const float* Fq = Fp + FELEMS;
            nx0 = p0 ? __ldg(xq + off0) : 0.f;
            nx1 = p1v ? __ldg(xq + off1) : 0.f;
            nfa = __ldg(Fq + f0);
            nfb = __ldg(Fq + f1);
            nfc = f2ok ? __ldg(Fq + f2) : 0.f;
        }

        // ---- compute on current buffers ----
#pragma unroll
        for (int rr = 0; rr < 3; ++rr) {
            const float* srow = &s_x[cur][(prow + rr) * SXSTRIDE + pcol];
            float4 a0 = *reinterpret_cast<const float4*>(srow);
            float4 a1 = *reinterpret_cast<const float4*>(srow + 4);
            float4 a2 = *reinterpret_cast<const float4*>(srow + 8);
            float2 a3 = *reinterpret_cast<const float2*>(srow + 12);
            float xv[14];
            xv[0] = a0.x; xv[1] = a0.y; xv[2] = a0.z; xv[3] = a0.w;
            xv[4] = a1.x; xv[5] = a1.y; xv[6] = a1.z; xv[7] = a1.w;
            xv[8] = a2.x; xv[9] = a2.y; xv[10] = a2.z; xv[11] = a2.w;
            xv[12] = a3.x; xv[13] = a3.y;
            unsigned long long xp2[13];
#pragma unroll
            for (int i = 0; i < 13; ++i) xp2[i] = pack2(xv[i], xv[i + 1]);

#pragma unroll
            for (int o = 0; o < OCT; ++o) {
                const unsigned long long* frow = reinterpret_cast<const unsigned long long*>(
                    &s_F[cur][((ocg * OCT + o) * 9 + rr * 3) * 2]);
#pragma unroll
                for (int kw = 0; kw < 3; ++kw) {
                    unsigned long long ff = frow[kw];
#pragma unroll
                    for (int j = 0; j < PX / 2; ++j)
                        acc[o][j] = ffma2(xp2[2 * j + kw], ff, acc[o][j]);
                }
            }
        }

        // ---- stage prefetched data into the other buffer ----
        if (more) {
            s_x[nxt][d0] = nx0;
            if (w1ok) s_x[nxt][d1] = nx1;
            s_F[nxt][f0] = nfa;
            s_F[nxt][f1] = nfb;
            if (f2ok) s_F[nxt][f2] = nfc;
            xp += PLANE;
            Fp += FELEMS;
        }
        __syncthreads();
    }

    // ---- epilogue ----
    const int h = ty0 + prow;
    const int w0 = tx0 + pcol;
#pragma unroll
    for (int o = 0; o < OCT; ++o) {
        const int oc = ocg * OCT + o;
        const float bo = b_out[oc];
        float v[12];
#pragma unroll
        for (int j = 0; j < PX / 2; ++j) {
            float lo, hi;
            unpack2(acc[o][j], lo, hi);
            v[2 * j] = lo + bo;
            v[2 * j + 1] = hi + bo;
        }
        float* op = out + (((size_t)(b * CHN + oc)) * HH + h) * WW + w0;
        reinterpret_cast<float4*>(op)[0] = make_float4(v[0], v[1], v[2], v[3]);
        reinterpret_cast<float4*>(op)[1] = make_float4(v[4], v[5], v[6], v[7]);
        reinterpret_cast<float4*>(op)[2] = make_float4(v[8], v[9], v[10], v[11]);
    }
}

// ---------------- launch ----------------
extern "C" void kernel_launch(void* const* d_in, const int* in_sizes, int n_in,
                              void* d_out, int out_size) {
    const float* x     = (const float*)d_in[0];
    const float* w1    = (const float*)d_in[1];
    const float* b1    = (const float*)d_in[2];
    const float* w2    = (const float*)d_in[3];
    const float* b2    = (const float*)d_in[4];
    const float* w3    = (const float*)d_in[5];
    const float* b3    = (const float*)d_in[6];
    const float* p1    = (const float*)d_in[7];
    const float* p2    = (const float*)d_in[8];
    const float* p3    = (const float*)d_in[9];
    const float* w_out = (const float*)d_in[10];
    const float* b_out = (const float*)d_in[11];
    float* out = (float*)d_out;

    gap_kernel<<<BATCH * CHN, 256>>>(x);
    filt1_kernel<<<(10800 + 255) / 256, 256>>>(w1, b1, w2, b2, w3, b3, p1, p2, p3);
    filt2_kernel<<<(32400 + 255) / 256, 256>>>(w_out);
    dim3 grid(WW / TW, HH / TH, BATCH);   // (2, 66, 20)
    conv_kernel<<<grid, THREADS>>>(x, b_out, out);
}